// round 13
// baseline (speedup 1.0000x reference)
#include <cuda_runtime.h>
#include <cstdint>

#define DT_C 0.02f
#define GRAV_C 10.0f
#define THRUST_C 6.0f
#define TORQUE_C 1.0f
#define TPB 64

__device__ __forceinline__ void cp_async16(uint32_t smem_dst, const void* gmem_src) {
    asm volatile("cp.async.cg.shared.global [%0], [%1], 16;"
                 :: "r"(smem_dst), "l"(gmem_src) : "memory");
}
__device__ __forceinline__ void cp_commit() {
    asm volatile("cp.async.commit_group;" ::: "memory");
}

__global__ __launch_bounds__(TPB, 12)
void ekf_kernel(const float* __restrict__ z, const float* __restrict__ u,
                const float* __restrict__ xprev, const float* __restrict__ Pprev,
                const float* __restrict__ qld, const float* __restrict__ qod,
                const float* __restrict__ rld, const float* __restrict__ rod,
                float* __restrict__ out_x, float* __restrict__ out_P, int B) {
    __shared__ float4 sP[2][TPB * 9];   // 18432 B
    __shared__ float sQ[36];
    __shared__ float sR[9];

    const int t = threadIdx.x;
    const int G = gridDim.x;
    const int bid = blockIdx.x;
    const int ntot = (B + TPB - 1) / TPB;
    const int nt = (ntot > bid) ? ((ntot - bid + G - 1) / G) : 0;

    // ---- Build Q = L L^T + 1e-6 I (threads 0..35) and R (36..44), once per CTA ----
    if (t < 36) {
        int i = t / 6, j = t % 6;
        float acc = (i == j) ? 1e-6f : 0.0f;
        #pragma unroll
        for (int k = 0; k < 6; k++) {
            float Lik = (k < i) ? qod[i * (i - 1) / 2 + k] : ((k == i) ? expf(qld[i]) : 0.0f);
            float Ljk = (k < j) ? qod[j * (j - 1) / 2 + k] : ((k == j) ? expf(qld[j]) : 0.0f);
            acc += Lik * Ljk;
        }
        sQ[t] = acc;
    } else if (t < 45) {
        int t2 = t - 36;
        int i = t2 / 3, j = t2 % 3;
        float acc = (i == j) ? 1e-6f : 0.0f;
        #pragma unroll
        for (int k = 0; k < 3; k++) {
            float Lik = (k < i) ? rod[i * (i - 1) / 2 + k] : ((k == i) ? expf(rld[i]) : 0.0f);
            float Ljk = (k < j) ? rod[j * (j - 1) / 2 + k] : ((k == j) ? expf(rld[j]) : 0.0f);
            acc += Lik * Ljk;
        }
        sR[t2] = acc;
    }

    if (nt == 0) return;

    auto issue_tile = [&](int k, int p) {
        int tile = bid + k * G;
        size_t base = (size_t)tile * TPB;
        if (base + TPB <= (size_t)B) {   // full tile: coalesced P staging
            const float4* Pg = reinterpret_cast<const float4*>(Pprev) + base * 9;
            uint32_t sb = (uint32_t)__cvta_generic_to_shared(&sP[p][0]);
            #pragma unroll
            for (int kk = 0; kk < 9; kk++)
                cp_async16(sb + (uint32_t)(t + kk * TPB) * 16u, Pg + t + kk * TPB);
        }
    };

    // ---- Prologue: prefetch first two tiles ----
    issue_tile(0, 0);
    cp_commit();
    if (nt > 1) issue_tile(1, 1);
    cp_commit();   // possibly empty; positional wait keeps group numbering consistent

    for (int k = 0; k < nt; k++) {
        int p = k & 1;
        int tile = bid + k * G;
        size_t base = (size_t)tile * TPB;
        bool full = (base + TPB <= (size_t)B);
        int b = (int)base + t;
        bool active = (b < B);

        // ---- Direct small loads (issued before the pipeline wait; overlap) ----
        float px = 0, py = 0, vx = 0, vy = 0, th = 0, om = 0;
        float u0 = 0, u1 = 0, z0 = 0, z1 = 0, z2 = 0;
        if (active) {
            const float2* x2 = reinterpret_cast<const float2*>(xprev + (size_t)b * 6);
            float2 a = x2[0], bb = x2[1], cc = x2[2];
            px = a.x; py = a.y; vx = bb.x; vy = bb.y; th = cc.x; om = cc.y;
            float2 uu = reinterpret_cast<const float2*>(u)[b];
            u0 = uu.x; u1 = uu.y;
            z0 = z[(size_t)b * 3 + 0];
            z1 = z[(size_t)b * 3 + 1];
            z2 = z[(size_t)b * 3 + 2];
        }

        // ---- Dynamics + Jacobian coefficients (independent of P; hides wait) ----
        float mp = fminf(fmaxf(u0, 0.0f), 1.0f);
        float s, c;
        __sincosf(th, &s, &c);
        float Tm = THRUST_C * mp;
        float nvx = vx + (-Tm * s) * DT_C;
        float nvy = vy + (Tm * c - GRAV_C) * DT_C;
        float nom = om + (TORQUE_C * u1) * DT_C;
        float npx = px + nvx * DT_C;
        float npy = py + nvy * DT_C;
        float nth = th + nom * DT_C;

        float a2 = -Tm * c * DT_C;   // F[2][4]
        float a3 = -Tm * s * DT_C;   // F[3][4]
        float a0 = a2 * DT_C;        // F[0][4]
        float a1 = a3 * DT_C;        // F[1][4]

        if (k + 1 < nt) asm volatile("cp.async.wait_group 1;" ::: "memory");
        else            asm volatile("cp.async.wait_group 0;" ::: "memory");
        __syncthreads();   // cross-thread: gather reads other threads' staged slots

        // ---- Fetch my P_prev ----
        float Pf[36];
        if (full) {
            #pragma unroll
            for (int i = 0; i < 9; i++) {
                float4 v = sP[p][t * 9 + i];
                Pf[4 * i + 0] = v.x; Pf[4 * i + 1] = v.y;
                Pf[4 * i + 2] = v.z; Pf[4 * i + 3] = v.w;
            }
        } else if (active) {
            const float4* p4 = reinterpret_cast<const float4*>(Pprev + (size_t)b * 36);
            #pragma unroll
            for (int i = 0; i < 9; i++) {
                float4 v = p4[i];
                Pf[4 * i + 0] = v.x; Pf[4 * i + 1] = v.y;
                Pf[4 * i + 2] = v.z; Pf[4 * i + 3] = v.w;
            }
        } else {
            #pragma unroll
            for (int i = 0; i < 36; i++) Pf[i] = 0.0f;
        }
#define Pm(i, j) Pf[(i) * 6 + (j)]

        // ---- P_pred = F P F^T + Q (sparse F: row ops then col ops, in place) ----
        #pragma unroll
        for (int j = 0; j < 6; j++) {
            Pm(0, j) += DT_C * Pm(2, j) + a0 * Pm(4, j);
            Pm(1, j) += DT_C * Pm(3, j) + a1 * Pm(4, j);
            Pm(2, j) += a2 * Pm(4, j);
            Pm(3, j) += a3 * Pm(4, j);
            Pm(4, j) += DT_C * Pm(5, j);
        }
        #pragma unroll
        for (int i = 0; i < 6; i++) {
            Pm(i, 0) += DT_C * Pm(i, 2) + a0 * Pm(i, 4);
            Pm(i, 1) += DT_C * Pm(i, 3) + a1 * Pm(i, 4);
            Pm(i, 2) += a2 * Pm(i, 4);
            Pm(i, 3) += a3 * Pm(i, 4);
            Pm(i, 4) += DT_C * Pm(i, 5);
        }

        // ---- Upper triangle of P_pred + Q ----
        float up[21];
        {
            int kk = 0;
            #pragma unroll
            for (int i = 0; i < 6; i++)
                #pragma unroll
                for (int j = i; j < 6; j++) {
                    up[kk] = Pm(i, j) + sQ[i * 6 + j];
                    kk++;
                }
        }
#undef Pm
#define UIDX(i, j) ((i) * 6 - (i) * ((i) + 1) / 2 + (j))
#define US(i, j) ((i) <= (j) ? up[UIDX(i, j)] : up[UIDX(j, i)])

        // ---- S = P_pred[(0,1,4),(0,1,4)] + R ; symmetric 3x3 inverse ----
        float S00 = US(0, 0) + sR[0];
        float S01 = US(0, 1) + sR[1];
        float S02 = US(0, 4) + sR[2];
        float S11 = US(1, 1) + sR[4];
        float S12 = US(1, 4) + sR[5];
        float S22 = US(4, 4) + sR[8];

        float i00 = S11 * S22 - S12 * S12;
        float i01 = S02 * S12 - S01 * S22;
        float i02 = S01 * S12 - S02 * S11;
        float i11 = S00 * S22 - S02 * S02;
        float i12 = S01 * S02 - S00 * S12;
        float i22 = S00 * S11 - S01 * S01;
        float invdet = 1.0f / (S00 * i00 + S01 * i01 + S02 * i02);
        i00 *= invdet; i01 *= invdet; i02 *= invdet;
        i11 *= invdet; i12 *= invdet; i22 *= invdet;

        // ---- K[k] = Si * (P[0][k], P[1][k], P[4][k]) ----
        float K[6][3];
        #pragma unroll
        for (int kk = 0; kk < 6; kk++) {
            float h0 = US(0, kk), h1 = US(1, kk), h2 = US(4, kk);
            K[kk][0] = h0 * i00 + h1 * i01 + h2 * i02;
            K[kk][1] = h0 * i01 + h1 * i11 + h2 * i12;
            K[kk][2] = h0 * i02 + h1 * i12 + h2 * i22;
        }

        // ---- x_upd (direct store, float2) ----
        float y0 = z0 - npx, y1 = z1 - npy, y2 = z2 - nth;
        if (active) {
            float xpred[6] = {npx, npy, nvx, nvy, nth, nom};
            float2* ox2 = reinterpret_cast<float2*>(out_x + (size_t)b * 6);
            #pragma unroll
            for (int i = 0; i < 3; i++) {
                float v0 = xpred[2 * i]     + K[2 * i][0] * y0 + K[2 * i][1] * y1 + K[2 * i][2] * y2;
                float v1 = xpred[2 * i + 1] + K[2 * i + 1][0] * y0 + K[2 * i + 1][1] * y1 + K[2 * i + 1][2] * y2;
                ox2[i] = make_float2(v0, v1);
            }
        }

        // ---- P_upd = P_pred - K (H P_pred), symmetric ----
        float Pu[36];
        #pragma unroll
        for (int i = 0; i < 6; i++)
            #pragma unroll
            for (int j = i; j < 6; j++) {
                float v = US(i, j)
                    - K[i][0] * US(0, j) - K[i][1] * US(1, j) - K[i][2] * US(4, j);
                Pu[i * 6 + j] = v;
                Pu[j * 6 + i] = v;
            }
#undef US
#undef UIDX

        // ---- P store ----
        if (full) {
            // stage into the just-consumed buffer (per-thread region), then coalesced STG
            #pragma unroll
            for (int i = 0; i < 9; i++)
                sP[p][t * 9 + i] = make_float4(Pu[4 * i], Pu[4 * i + 1], Pu[4 * i + 2], Pu[4 * i + 3]);
            __syncthreads();   // cross-thread: STG phase reads other threads' slots
            float4* Po = reinterpret_cast<float4*>(out_P) + base * 9;
            #pragma unroll
            for (int kk = 0; kk < 9; kk++)
                Po[t + kk * TPB] = sP[p][t + kk * TPB];
            // No block barrier: the k+2 prefetch writes slot sP[p][t + kk*TPB] —
            // exactly the slots THIS thread just read for its STGs (no cross-thread
            // hazard; per-thread LDS issues before the LDGSTS smem write can land).
            __syncwarp();
        } else if (active) {
            float4* op4 = reinterpret_cast<float4*>(out_P + (size_t)b * 36);
            #pragma unroll
            for (int i = 0; i < 9; i++)
                op4[i] = make_float4(Pu[4 * i], Pu[4 * i + 1], Pu[4 * i + 2], Pu[4 * i + 3]);
        }

        // ---- Prefetch tile k+2 into buffer p ----
        if (k + 2 < nt) issue_tile(k + 2, p);
        cp_commit();
    }
}

extern "C" void kernel_launch(void* const* d_in, const int* in_sizes, int n_in,
                              void* d_out, int out_size) {
    const float* z   = (const float*)d_in[0];
    const float* u   = (const float*)d_in[1];
    const float* xp  = (const float*)d_in[2];
    const float* Pp  = (const float*)d_in[3];
    const float* qld = (const float*)d_in[4];
    const float* qod = (const float*)d_in[5];
    const float* rld = (const float*)d_in[6];
    const float* rod = (const float*)d_in[7];

    int B = in_sizes[0] / 3;
    float* out_x = (float*)d_out;
    float* out_P = out_x + (size_t)B * 6;

    int ntot = (B + TPB - 1) / TPB;
    int grid = 1824;                // 12 CTAs/SM x 152 SMs, all resident in wave 1
    if (grid > ntot) grid = ntot;

    ekf_kernel<<<grid, TPB>>>(z, u, xp, Pp, qld, qod, rld, rod, out_x, out_P, B);
}

// round 14
// speedup vs baseline: 1.1138x; 1.1138x over previous
#include <cuda_runtime.h>
#include <cstdint>

#define DT_C 0.02f
#define GRAV_C 10.0f
#define THRUST_C 6.0f
#define TORQUE_C 1.0f
#define TPB 128

__device__ __forceinline__ void cp_async16(uint32_t smem_dst, const void* gmem_src) {
    asm volatile("cp.async.cg.shared.global [%0], [%1], 16;"
                 :: "r"(smem_dst), "l"(gmem_src) : "memory");
}
__device__ __forceinline__ void cp_commit() {
    asm volatile("cp.async.commit_group;" ::: "memory");
}

__global__ __launch_bounds__(TPB, 6)
void ekf_kernel(const float* __restrict__ z, const float* __restrict__ u,
                const float* __restrict__ xprev, const float* __restrict__ Pprev,
                const float* __restrict__ qld, const float* __restrict__ qod,
                const float* __restrict__ rld, const float* __restrict__ rod,
                float* __restrict__ out_x, float* __restrict__ out_P, int B) {
    __shared__ float4 sP[2][TPB * 9];   // 36864 B
    __shared__ float sQ[36];
    __shared__ float sR[9];

    const int t = threadIdx.x;
    const int G = gridDim.x;
    const int bid = blockIdx.x;
    const int ntot = (B + TPB - 1) / TPB;
    const int nt = (ntot > bid) ? ((ntot - bid + G - 1) / G) : 0;

    // ---- Build Q = L L^T + 1e-6 I (threads 0..35) and R (36..44), once per CTA ----
    if (t < 36) {
        int i = t / 6, j = t % 6;
        float acc = (i == j) ? 1e-6f : 0.0f;
        #pragma unroll
        for (int k = 0; k < 6; k++) {
            float Lik = (k < i) ? qod[i * (i - 1) / 2 + k] : ((k == i) ? expf(qld[i]) : 0.0f);
            float Ljk = (k < j) ? qod[j * (j - 1) / 2 + k] : ((k == j) ? expf(qld[j]) : 0.0f);
            acc += Lik * Ljk;
        }
        sQ[t] = acc;
    } else if (t < 45) {
        int t2 = t - 36;
        int i = t2 / 3, j = t2 % 3;
        float acc = (i == j) ? 1e-6f : 0.0f;
        #pragma unroll
        for (int k = 0; k < 3; k++) {
            float Lik = (k < i) ? rod[i * (i - 1) / 2 + k] : ((k == i) ? expf(rld[i]) : 0.0f);
            float Ljk = (k < j) ? rod[j * (j - 1) / 2 + k] : ((k == j) ? expf(rld[j]) : 0.0f);
            acc += Lik * Ljk;
        }
        sR[t2] = acc;
    }

    if (nt == 0) return;

    auto issue_tile = [&](int k, int p) {
        int tile = bid + k * G;
        size_t base = (size_t)tile * TPB;
        if (base + TPB <= (size_t)B) {   // full tile: coalesced P staging
            const float4* Pg = reinterpret_cast<const float4*>(Pprev) + base * 9;
            uint32_t sb = (uint32_t)__cvta_generic_to_shared(&sP[p][0]);
            #pragma unroll
            for (int kk = 0; kk < 9; kk++)
                cp_async16(sb + (uint32_t)(t + kk * TPB) * 16u, Pg + t + kk * TPB);
        }
    };

    // ---- Prologue: prefetch first two tiles ----
    issue_tile(0, 0);
    cp_commit();
    if (nt > 1) issue_tile(1, 1);
    cp_commit();   // possibly empty; positional wait keeps group numbering consistent

    for (int k = 0; k < nt; k++) {
        int p = k & 1;
        int tile = bid + k * G;
        size_t base = (size_t)tile * TPB;
        bool full = (base + TPB <= (size_t)B);
        int b = (int)base + t;
        bool active = (b < B);

        // ---- Direct small loads (issued before the pipeline wait; overlap) ----
        float px = 0, py = 0, vx = 0, vy = 0, th = 0, om = 0;
        float u0 = 0, u1 = 0, z0 = 0, z1 = 0, z2 = 0;
        if (active) {
            const float2* x2 = reinterpret_cast<const float2*>(xprev + (size_t)b * 6);
            float2 a = x2[0], bb = x2[1], cc = x2[2];
            px = a.x; py = a.y; vx = bb.x; vy = bb.y; th = cc.x; om = cc.y;
            float2 uu = reinterpret_cast<const float2*>(u)[b];
            u0 = uu.x; u1 = uu.y;
            z0 = z[(size_t)b * 3 + 0];
            z1 = z[(size_t)b * 3 + 1];
            z2 = z[(size_t)b * 3 + 2];
        }

        // ---- Dynamics + Jacobian coefficients (independent of P; hides wait) ----
        float mp = fminf(fmaxf(u0, 0.0f), 1.0f);
        float s, c;
        __sincosf(th, &s, &c);
        float Tm = THRUST_C * mp;
        float nvx = vx + (-Tm * s) * DT_C;
        float nvy = vy + (Tm * c - GRAV_C) * DT_C;
        float nom = om + (TORQUE_C * u1) * DT_C;
        float npx = px + nvx * DT_C;
        float npy = py + nvy * DT_C;
        float nth = th + nom * DT_C;

        float a2 = -Tm * c * DT_C;   // F[2][4]
        float a3 = -Tm * s * DT_C;   // F[3][4]
        float a0 = a2 * DT_C;        // F[0][4]
        float a1 = a3 * DT_C;        // F[1][4]

        if (k + 1 < nt) asm volatile("cp.async.wait_group 1;" ::: "memory");
        else            asm volatile("cp.async.wait_group 0;" ::: "memory");
        __syncthreads();   // cross-thread: gather reads other threads' staged slots

        // ---- Fetch my P_prev ----
        float Pf[36];
        if (full) {
            #pragma unroll
            for (int i = 0; i < 9; i++) {
                float4 v = sP[p][t * 9 + i];
                Pf[4 * i + 0] = v.x; Pf[4 * i + 1] = v.y;
                Pf[4 * i + 2] = v.z; Pf[4 * i + 3] = v.w;
            }
        } else if (active) {
            const float4* p4 = reinterpret_cast<const float4*>(Pprev + (size_t)b * 36);
            #pragma unroll
            for (int i = 0; i < 9; i++) {
                float4 v = p4[i];
                Pf[4 * i + 0] = v.x; Pf[4 * i + 1] = v.y;
                Pf[4 * i + 2] = v.z; Pf[4 * i + 3] = v.w;
            }
        } else {
            #pragma unroll
            for (int i = 0; i < 36; i++) Pf[i] = 0.0f;
        }
#define Pm(i, j) Pf[(i) * 6 + (j)]

        // ---- P_pred = F P F^T + Q (sparse F: row ops then col ops, in place) ----
        #pragma unroll
        for (int j = 0; j < 6; j++) {
            Pm(0, j) += DT_C * Pm(2, j) + a0 * Pm(4, j);
            Pm(1, j) += DT_C * Pm(3, j) + a1 * Pm(4, j);
            Pm(2, j) += a2 * Pm(4, j);
            Pm(3, j) += a3 * Pm(4, j);
            Pm(4, j) += DT_C * Pm(5, j);
        }
        #pragma unroll
        for (int i = 0; i < 6; i++) {
            Pm(i, 0) += DT_C * Pm(i, 2) + a0 * Pm(i, 4);
            Pm(i, 1) += DT_C * Pm(i, 3) + a1 * Pm(i, 4);
            Pm(i, 2) += a2 * Pm(i, 4);
            Pm(i, 3) += a3 * Pm(i, 4);
            Pm(i, 4) += DT_C * Pm(i, 5);
        }

        // ---- Upper triangle of P_pred + Q ----
        float up[21];
        {
            int kk = 0;
            #pragma unroll
            for (int i = 0; i < 6; i++)
                #pragma unroll
                for (int j = i; j < 6; j++) {
                    up[kk] = Pm(i, j) + sQ[i * 6 + j];
                    kk++;
                }
        }
#undef Pm
#define UIDX(i, j) ((i) * 6 - (i) * ((i) + 1) / 2 + (j))
#define US(i, j) ((i) <= (j) ? up[UIDX(i, j)] : up[UIDX(j, i)])

        // ---- S = P_pred[(0,1,4),(0,1,4)] + R ; symmetric 3x3 inverse ----
        float S00 = US(0, 0) + sR[0];
        float S01 = US(0, 1) + sR[1];
        float S02 = US(0, 4) + sR[2];
        float S11 = US(1, 1) + sR[4];
        float S12 = US(1, 4) + sR[5];
        float S22 = US(4, 4) + sR[8];

        float i00 = S11 * S22 - S12 * S12;
        float i01 = S02 * S12 - S01 * S22;
        float i02 = S01 * S12 - S02 * S11;
        float i11 = S00 * S22 - S02 * S02;
        float i12 = S01 * S02 - S00 * S12;
        float i22 = S00 * S11 - S01 * S01;
        float invdet = 1.0f / (S00 * i00 + S01 * i01 + S02 * i02);
        i00 *= invdet; i01 *= invdet; i02 *= invdet;
        i11 *= invdet; i12 *= invdet; i22 *= invdet;

        // ---- K[k] = Si * (P[0][k], P[1][k], P[4][k]) ----
        float K[6][3];
        #pragma unroll
        for (int kk = 0; kk < 6; kk++) {
            float h0 = US(0, kk), h1 = US(1, kk), h2 = US(4, kk);
            K[kk][0] = h0 * i00 + h1 * i01 + h2 * i02;
            K[kk][1] = h0 * i01 + h1 * i11 + h2 * i12;
            K[kk][2] = h0 * i02 + h1 * i12 + h2 * i22;
        }

        // ---- x_upd (direct store, float2) ----
        float y0 = z0 - npx, y1 = z1 - npy, y2 = z2 - nth;
        if (active) {
            float xpred[6] = {npx, npy, nvx, nvy, nth, nom};
            float2* ox2 = reinterpret_cast<float2*>(out_x + (size_t)b * 6);
            #pragma unroll
            for (int i = 0; i < 3; i++) {
                float v0 = xpred[2 * i]     + K[2 * i][0] * y0 + K[2 * i][1] * y1 + K[2 * i][2] * y2;
                float v1 = xpred[2 * i + 1] + K[2 * i + 1][0] * y0 + K[2 * i + 1][1] * y1 + K[2 * i + 1][2] * y2;
                ox2[i] = make_float2(v0, v1);
            }
        }

        // ---- P_upd = P_pred - K (H P_pred), symmetric ----
        float Pu[36];
        #pragma unroll
        for (int i = 0; i < 6; i++)
            #pragma unroll
            for (int j = i; j < 6; j++) {
                float v = US(i, j)
                    - K[i][0] * US(0, j) - K[i][1] * US(1, j) - K[i][2] * US(4, j);
                Pu[i * 6 + j] = v;
                Pu[j * 6 + i] = v;
            }
#undef US
#undef UIDX

        // ---- P store ----
        if (full) {
            // stage into the just-consumed buffer (per-thread region), then coalesced STG
            #pragma unroll
            for (int i = 0; i < 9; i++)
                sP[p][t * 9 + i] = make_float4(Pu[4 * i], Pu[4 * i + 1], Pu[4 * i + 2], Pu[4 * i + 3]);
            __syncthreads();   // cross-thread: STG phase reads other threads' slots
            float4* Po = reinterpret_cast<float4*>(out_P) + base * 9;
            #pragma unroll
            for (int kk = 0; kk < 9; kk++)
                Po[t + kk * TPB] = sP[p][t + kk * TPB];
            // No block barrier: the k+2 prefetch writes slot sP[p][t + kk*128] —
            // exactly the slots THIS thread just read for its STGs (no cross-thread
            // hazard; per-thread LDS issues before the LDGSTS smem write can land).
            __syncwarp();
        } else if (active) {
            float4* op4 = reinterpret_cast<float4*>(out_P + (size_t)b * 36);
            #pragma unroll
            for (int i = 0; i < 9; i++)
                op4[i] = make_float4(Pu[4 * i], Pu[4 * i + 1], Pu[4 * i + 2], Pu[4 * i + 3]);
        }

        // ---- Prefetch tile k+2 into buffer p ----
        if (k + 2 < nt) issue_tile(k + 2, p);
        cp_commit();
    }
}

extern "C" void kernel_launch(void* const* d_in, const int* in_sizes, int n_in,
                              void* d_out, int out_size) {
    const float* z   = (const float*)d_in[0];
    const float* u   = (const float*)d_in[1];
    const float* xp  = (const float*)d_in[2];
    const float* Pp  = (const float*)d_in[3];
    const float* qld = (const float*)d_in[4];
    const float* qod = (const float*)d_in[5];
    const float* rld = (const float*)d_in[6];
    const float* rod = (const float*)d_in[7];

    int B = in_sizes[0] / 3;
    float* out_x = (float*)d_out;
    float* out_P = out_x + (size_t)B * 6;

    int ntot = (B + TPB - 1) / TPB;
    int grid = 912;                 // 6 CTAs/SM x 152 SMs, all resident in wave 1
    if (grid > ntot) grid = ntot;

    ekf_kernel<<<grid, TPB>>>(z, u, xp, Pp, qld, qod, rld, rod, out_x, out_P, B);
}

// round 15
// speedup vs baseline: 1.1199x; 1.0055x over previous
#include <cuda_runtime.h>
#include <cstdint>

#define DT_C 0.02f
#define GRAV_C 10.0f
#define THRUST_C 6.0f
#define TORQUE_C 1.0f
#define TPB 128

__device__ __forceinline__ void cp_async16(uint32_t smem_dst, const void* gmem_src) {
    asm volatile("cp.async.cg.shared.global [%0], [%1], 16;"
                 :: "r"(smem_dst), "l"(gmem_src) : "memory");
}
__device__ __forceinline__ void cp_commit() {
    asm volatile("cp.async.commit_group;" ::: "memory");
}

__global__ __launch_bounds__(TPB, 4)
void ekf_kernel(const float* __restrict__ z, const float* __restrict__ u,
                const float* __restrict__ xprev, const float* __restrict__ Pprev,
                const float* __restrict__ qld, const float* __restrict__ qod,
                const float* __restrict__ rld, const float* __restrict__ rod,
                float* __restrict__ out_x, float* __restrict__ out_P, int B) {
    __shared__ float4 sP[2][TPB * 9];    // 36864 B input double-buffer
    __shared__ float4 sOut[TPB * 9];     // 18432 B output staging (decouples STG from prefetch)
    __shared__ float sQ[36];
    __shared__ float sR[9];

    const int t = threadIdx.x;
    const int G = gridDim.x;
    const int bid = blockIdx.x;
    const int ntot = (B + TPB - 1) / TPB;
    const int nt = (ntot > bid) ? ((ntot - bid + G - 1) / G) : 0;

    // ---- Build Q = L L^T + 1e-6 I (threads 0..35) and R (36..44), once per CTA ----
    if (t < 36) {
        int i = t / 6, j = t % 6;
        float acc = (i == j) ? 1e-6f : 0.0f;
        #pragma unroll
        for (int k = 0; k < 6; k++) {
            float Lik = (k < i) ? qod[i * (i - 1) / 2 + k] : ((k == i) ? expf(qld[i]) : 0.0f);
            float Ljk = (k < j) ? qod[j * (j - 1) / 2 + k] : ((k == j) ? expf(qld[j]) : 0.0f);
            acc += Lik * Ljk;
        }
        sQ[t] = acc;
    } else if (t < 45) {
        int t2 = t - 36;
        int i = t2 / 3, j = t2 % 3;
        float acc = (i == j) ? 1e-6f : 0.0f;
        #pragma unroll
        for (int k = 0; k < 3; k++) {
            float Lik = (k < i) ? rod[i * (i - 1) / 2 + k] : ((k == i) ? expf(rld[i]) : 0.0f);
            float Ljk = (k < j) ? rod[j * (j - 1) / 2 + k] : ((k == j) ? expf(rld[j]) : 0.0f);
            acc += Lik * Ljk;
        }
        sR[t2] = acc;
    }

    if (nt == 0) return;

    auto issue_tile = [&](int k, int p) {
        int tile = bid + k * G;
        size_t base = (size_t)tile * TPB;
        if (base + TPB <= (size_t)B) {   // full tile: coalesced P staging
            const float4* Pg = reinterpret_cast<const float4*>(Pprev) + base * 9;
            uint32_t sb = (uint32_t)__cvta_generic_to_shared(&sP[p][0]);
            #pragma unroll
            for (int kk = 0; kk < 9; kk++)
                cp_async16(sb + (uint32_t)(t + kk * TPB) * 16u, Pg + t + kk * TPB);
        }
    };

    // ---- Prologue: prefetch first two tiles ----
    issue_tile(0, 0);
    cp_commit();
    if (nt > 1) issue_tile(1, 1);
    cp_commit();   // possibly empty; positional wait keeps group numbering consistent

    for (int k = 0; k < nt; k++) {
        int p = k & 1;
        int tile = bid + k * G;
        size_t base = (size_t)tile * TPB;
        bool full = (base + TPB <= (size_t)B);
        int b = (int)base + t;
        bool active = (b < B);

        // ---- Direct small loads (issued before the pipeline wait; overlap) ----
        float px = 0, py = 0, vx = 0, vy = 0, th = 0, om = 0;
        float u0 = 0, u1 = 0, z0 = 0, z1 = 0, z2 = 0;
        if (active) {
            const float2* x2 = reinterpret_cast<const float2*>(xprev + (size_t)b * 6);
            float2 a = x2[0], bb = x2[1], cc = x2[2];
            px = a.x; py = a.y; vx = bb.x; vy = bb.y; th = cc.x; om = cc.y;
            float2 uu = reinterpret_cast<const float2*>(u)[b];
            u0 = uu.x; u1 = uu.y;
            z0 = z[(size_t)b * 3 + 0];
            z1 = z[(size_t)b * 3 + 1];
            z2 = z[(size_t)b * 3 + 2];
        }

        if (k + 1 < nt) asm volatile("cp.async.wait_group 1;" ::: "memory");
        else            asm volatile("cp.async.wait_group 0;" ::: "memory");
        __syncthreads();   // staged tile k visible to all threads

        // ---- Gather my P_prev out of buffer p ----
        float Pf[36];
        if (full) {
            #pragma unroll
            for (int i = 0; i < 9; i++) {
                float4 v = sP[p][t * 9 + i];
                Pf[4 * i + 0] = v.x; Pf[4 * i + 1] = v.y;
                Pf[4 * i + 2] = v.z; Pf[4 * i + 3] = v.w;
            }
        } else if (active) {
            const float4* p4 = reinterpret_cast<const float4*>(Pprev + (size_t)b * 36);
            #pragma unroll
            for (int i = 0; i < 9; i++) {
                float4 v = p4[i];
                Pf[4 * i + 0] = v.x; Pf[4 * i + 1] = v.y;
                Pf[4 * i + 2] = v.z; Pf[4 * i + 3] = v.w;
            }
        } else {
            #pragma unroll
            for (int i = 0; i < 36; i++) Pf[i] = 0.0f;
        }
        __syncthreads();   // all gathers done: buffer p is free for the k+2 prefetch

        // ---- EARLY prefetch of tile k+2 into buffer p (2 tiles now in flight) ----
        if (k + 2 < nt) issue_tile(k + 2, p);
        cp_commit();

#define Pm(i, j) Pf[(i) * 6 + (j)]
        // ---- Dynamics + Jacobian coefficients ----
        float mp = fminf(fmaxf(u0, 0.0f), 1.0f);
        float s, c;
        __sincosf(th, &s, &c);
        float Tm = THRUST_C * mp;
        float nvx = vx + (-Tm * s) * DT_C;
        float nvy = vy + (Tm * c - GRAV_C) * DT_C;
        float nom = om + (TORQUE_C * u1) * DT_C;
        float npx = px + nvx * DT_C;
        float npy = py + nvy * DT_C;
        float nth = th + nom * DT_C;

        float a2 = -Tm * c * DT_C;   // F[2][4]
        float a3 = -Tm * s * DT_C;   // F[3][4]
        float a0 = a2 * DT_C;        // F[0][4]
        float a1 = a3 * DT_C;        // F[1][4]

        // ---- P_pred = F P F^T + Q (sparse F: row ops then col ops, in place) ----
        #pragma unroll
        for (int j = 0; j < 6; j++) {
            Pm(0, j) += DT_C * Pm(2, j) + a0 * Pm(4, j);
            Pm(1, j) += DT_C * Pm(3, j) + a1 * Pm(4, j);
            Pm(2, j) += a2 * Pm(4, j);
            Pm(3, j) += a3 * Pm(4, j);
            Pm(4, j) += DT_C * Pm(5, j);
        }
        #pragma unroll
        for (int i = 0; i < 6; i++) {
            Pm(i, 0) += DT_C * Pm(i, 2) + a0 * Pm(i, 4);
            Pm(i, 1) += DT_C * Pm(i, 3) + a1 * Pm(i, 4);
            Pm(i, 2) += a2 * Pm(i, 4);
            Pm(i, 3) += a3 * Pm(i, 4);
            Pm(i, 4) += DT_C * Pm(i, 5);
        }

        // ---- Upper triangle of P_pred + Q ----
        float up[21];
        {
            int kk = 0;
            #pragma unroll
            for (int i = 0; i < 6; i++)
                #pragma unroll
                for (int j = i; j < 6; j++) {
                    up[kk] = Pm(i, j) + sQ[i * 6 + j];
                    kk++;
                }
        }
#undef Pm
#define UIDX(i, j) ((i) * 6 - (i) * ((i) + 1) / 2 + (j))
#define US(i, j) ((i) <= (j) ? up[UIDX(i, j)] : up[UIDX(j, i)])

        // ---- S = P_pred[(0,1,4),(0,1,4)] + R ; symmetric 3x3 inverse ----
        float S00 = US(0, 0) + sR[0];
        float S01 = US(0, 1) + sR[1];
        float S02 = US(0, 4) + sR[2];
        float S11 = US(1, 1) + sR[4];
        float S12 = US(1, 4) + sR[5];
        float S22 = US(4, 4) + sR[8];

        float i00 = S11 * S22 - S12 * S12;
        float i01 = S02 * S12 - S01 * S22;
        float i02 = S01 * S12 - S02 * S11;
        float i11 = S00 * S22 - S02 * S02;
        float i12 = S01 * S02 - S00 * S12;
        float i22 = S00 * S11 - S01 * S01;
        float invdet = 1.0f / (S00 * i00 + S01 * i01 + S02 * i02);
        i00 *= invdet; i01 *= invdet; i02 *= invdet;
        i11 *= invdet; i12 *= invdet; i22 *= invdet;

        // ---- K[k] = Si * (P[0][k], P[1][k], P[4][k]) ----
        float K[6][3];
        #pragma unroll
        for (int kk = 0; kk < 6; kk++) {
            float h0 = US(0, kk), h1 = US(1, kk), h2 = US(4, kk);
            K[kk][0] = h0 * i00 + h1 * i01 + h2 * i02;
            K[kk][1] = h0 * i01 + h1 * i11 + h2 * i12;
            K[kk][2] = h0 * i02 + h1 * i12 + h2 * i22;
        }

        // ---- x_upd (direct store, float2) ----
        float y0 = z0 - npx, y1 = z1 - npy, y2 = z2 - nth;
        if (active) {
            float xpred[6] = {npx, npy, nvx, nvy, nth, nom};
            float2* ox2 = reinterpret_cast<float2*>(out_x + (size_t)b * 6);
            #pragma unroll
            for (int i = 0; i < 3; i++) {
                float v0 = xpred[2 * i]     + K[2 * i][0] * y0 + K[2 * i][1] * y1 + K[2 * i][2] * y2;
                float v1 = xpred[2 * i + 1] + K[2 * i + 1][0] * y0 + K[2 * i + 1][1] * y1 + K[2 * i + 1][2] * y2;
                ox2[i] = make_float2(v0, v1);
            }
        }

        // ---- P_upd = P_pred - K (H P_pred), symmetric ----
        float Pu[36];
        #pragma unroll
        for (int i = 0; i < 6; i++)
            #pragma unroll
            for (int j = i; j < 6; j++) {
                float v = US(i, j)
                    - K[i][0] * US(0, j) - K[i][1] * US(1, j) - K[i][2] * US(4, j);
                Pu[i * 6 + j] = v;
                Pu[j * 6 + i] = v;
            }
#undef US
#undef UIDX

        // ---- P store via dedicated output buffer (input buffers untouched) ----
        if (full) {
            #pragma unroll
            for (int i = 0; i < 9; i++)
                sOut[t * 9 + i] = make_float4(Pu[4 * i], Pu[4 * i + 1], Pu[4 * i + 2], Pu[4 * i + 3]);
            __syncthreads();   // cross-thread: STG phase reads other threads' slots
            float4* Po = reinterpret_cast<float4*>(out_P) + base * 9;
            #pragma unroll
            for (int kk = 0; kk < 9; kk++)
                Po[t + kk * TPB] = sOut[t + kk * TPB];
            // Next iteration's re-staging of sOut is ordered by the wait+syncthreads
            // at the top of the loop; no extra barrier needed here.
        } else if (active) {
            float4* op4 = reinterpret_cast<float4*>(out_P + (size_t)b * 36);
            #pragma unroll
            for (int i = 0; i < 9; i++)
                op4[i] = make_float4(Pu[4 * i], Pu[4 * i + 1], Pu[4 * i + 2], Pu[4 * i + 3]);
        }
    }
}

extern "C" void kernel_launch(void* const* d_in, const int* in_sizes, int n_in,
                              void* d_out, int out_size) {
    const float* z   = (const float*)d_in[0];
    const float* u   = (const float*)d_in[1];
    const float* xp  = (const float*)d_in[2];
    const float* Pp  = (const float*)d_in[3];
    const float* qld = (const float*)d_in[4];
    const float* qod = (const float*)d_in[5];
    const float* rld = (const float*)d_in[6];
    const float* rod = (const float*)d_in[7];

    int B = in_sizes[0] / 3;
    float* out_x = (float*)d_out;
    float* out_P = out_x + (size_t)B * 6;

    int ntot = (B + TPB - 1) / TPB;
    int grid = 608;                 // 4 CTAs/SM x 152 SMs (55.4 KB smem/CTA)
    if (grid > ntot) grid = ntot;

    ekf_kernel<<<grid, TPB>>>(z, u, xp, Pp, qld, qod, rld, rod, out_x, out_P, B);
}